// round 9
// baseline (speedup 1.0000x reference)
#include <cuda_runtime.h>

// DifferentiableTTFSEncoder: first-fire one-hot over T=64 steps.
// out[b, t, n] = 1.0f at the first t where the exact-fp32 LIF recurrence
// mem = fmaf(mem, d, c*(1-d)), c = x[b,n]*sens[n], crosses 1.0; else 0.
//
// Store-wall kernel (512 MB write-once output; ~6.0 TB/s wall measured
// across R1-R8: width/pacing/occupancy/waves/.cs/.wt all equivalent).
// R9: probe DRAM row-buffer locality — batch 4 t-steps in registers and
// issue their 4 STG.128.CS back-to-back, so each block presents 16 KB
// same-region write bursts instead of 4 KB. Traffic, mapping, and the
// bit-exact recurrence are unchanged; every line still touched once.

#define B_DIM 2048
#define N_DIM 1024
#define T_DIM 64
#define NQ    (N_DIM / 4)   // float4 groups per row = 256
#define TB    4             // t-steps batched per store burst

__global__ void __launch_bounds__(256)
ttfs_kernel(const float* __restrict__ x,
            const float* __restrict__ sens,
            float* __restrict__ out)
{
    const int gid = blockIdx.x * blockDim.x + threadIdx.x;  // over B*N/4
    const int b  = gid >> 8;        // / NQ (NQ = 256)
    const int nq = gid & (NQ - 1);  // % NQ

    // Inputs (coalesced float4)
    const float4 xv = reinterpret_cast<const float4*>(x)[gid];
    const float4 sv = reinterpret_cast<const float4*>(sens)[nq];

    const float d   = 0.60653065971263342360f;  // exp(-0.5), fp32-rounded
    const float omd = 1.0f - d;

    // Per-element constant drive c*(1-d)
    const float cc0 = xv.x * sv.x * omd;
    const float cc1 = xv.y * sv.y * omd;
    const float cc2 = xv.z * sv.z * omd;
    const float cc3 = xv.w * sv.w * omd;

    float m0 = 0.0f, m1 = 0.0f, m2 = 0.0f, m3 = 0.0f;
    bool  f0 = false, f1 = false, f2 = false, f3 = false;

    // Output base: out[b, t, n] with n = nq*4; stride per t is N_DIM floats
    float4* op = reinterpret_cast<float4*>(out)
               + (size_t)b * (size_t)T_DIM * NQ + nq;

    #pragma unroll
    for (int tb = 0; tb < T_DIM / TB; ++tb) {
        float4 v[TB];

        // Compute TB steps into registers (dependent chain, no stores yet)
        #pragma unroll
        for (int j = 0; j < TB; ++j) {
            m0 = fmaf(m0, d, cc0);
            m1 = fmaf(m1, d, cc1);
            m2 = fmaf(m2, d, cc2);
            m3 = fmaf(m3, d, cc3);

            const bool s0 = (m0 >= 1.0f);
            const bool s1 = (m1 >= 1.0f);
            const bool s2 = (m2 >= 1.0f);
            const bool s3 = (m3 >= 1.0f);

            v[j].x = (s0 && !f0) ? 1.0f : 0.0f;
            v[j].y = (s1 && !f1) ? 1.0f : 0.0f;
            v[j].z = (s2 && !f2) ? 1.0f : 0.0f;
            v[j].w = (s3 && !f3) ? 1.0f : 0.0f;

            f0 = f0 || s0;
            f1 = f1 || s1;
            f2 = f2 || s2;
            f3 = f3 || s3;
        }

        // Burst: 4 consecutive-t evict-first stores back-to-back (16 KB/block)
        #pragma unroll
        for (int j = 0; j < TB; ++j) {
            __stcs(op + (size_t)(tb * TB + j) * NQ, v[j]);
        }
    }
}

extern "C" void kernel_launch(void* const* d_in, const int* in_sizes, int n_in,
                              void* d_out, int out_size)
{
    const float* x    = (const float*)d_in[0];   // [2048, 1024] f32
    const float* sens = (const float*)d_in[1];   // [1024] f32
    float* out        = (float*)d_out;           // [2048, 64, 1024] f32

    const int total_threads = (B_DIM * N_DIM) / 4;  // 524288
    const int block = 256;
    const int grid  = total_threads / block;        // 2048

    ttfs_kernel<<<grid, block>>>(x, sens, out);
}

// round 10
// speedup vs baseline: 1.1353x; 1.1353x over previous
#include <cuda_runtime.h>

// DifferentiableTTFSEncoder: first-fire one-hot over T=64 steps.
// out[b, t, n] = 1.0f at the first t where the exact-fp32 LIF recurrence
// mem = fmaf(mem, d, c*(1-d)), c = x[b,n]*sens[n], crosses 1.0; else 0.
//
// Store-wall kernel: 512 MB write-once output, measured wall ~6.0 TB/s
// across 9 experiments (width/pacing/bursting/occupancy/waves/.cs/.wt all
// within noise; interleaved 1-store-per-step STG.128 is the best pattern).
// R10: recombine the two best variants — R1's natural register allocation
// (no min-blocks hint; lowest measured kernel dur 79.9us) with R7's
// evict-first .cs stores (best measured wall 81.9us).

#define B_DIM 2048
#define N_DIM 1024
#define T_DIM 64
#define NQ    (N_DIM / 4)   // float4 groups per row = 256

__global__ void __launch_bounds__(256)
ttfs_kernel(const float* __restrict__ x,
            const float* __restrict__ sens,
            float* __restrict__ out)
{
    const int gid = blockIdx.x * blockDim.x + threadIdx.x;  // over B*N/4
    const int b  = gid >> 8;        // / NQ (NQ = 256)
    const int nq = gid & (NQ - 1);  // % NQ

    // Inputs (coalesced float4)
    const float4 xv = reinterpret_cast<const float4*>(x)[gid];
    const float4 sv = reinterpret_cast<const float4*>(sens)[nq];

    const float d   = 0.60653065971263342360f;  // exp(-0.5), fp32-rounded
    const float omd = 1.0f - d;

    // Per-element constant drive c*(1-d)
    const float cc0 = xv.x * sv.x * omd;
    const float cc1 = xv.y * sv.y * omd;
    const float cc2 = xv.z * sv.z * omd;
    const float cc3 = xv.w * sv.w * omd;

    float m0 = 0.0f, m1 = 0.0f, m2 = 0.0f, m3 = 0.0f;
    bool  f0 = false, f1 = false, f2 = false, f3 = false;

    // Output base: out[b, t, n] with n = nq*4; stride per t is N_DIM floats
    float4* op = reinterpret_cast<float4*>(out)
               + (size_t)b * (size_t)T_DIM * NQ + nq;

    #pragma unroll
    for (int t = 0; t < T_DIM; ++t) {
        m0 = fmaf(m0, d, cc0);
        m1 = fmaf(m1, d, cc1);
        m2 = fmaf(m2, d, cc2);
        m3 = fmaf(m3, d, cc3);

        const bool s0 = (m0 >= 1.0f);
        const bool s1 = (m1 >= 1.0f);
        const bool s2 = (m2 >= 1.0f);
        const bool s3 = (m3 >= 1.0f);

        float4 v;
        v.x = (s0 && !f0) ? 1.0f : 0.0f;
        v.y = (s1 && !f1) ? 1.0f : 0.0f;
        v.z = (s2 && !f2) ? 1.0f : 0.0f;
        v.w = (s3 && !f3) ? 1.0f : 0.0f;

        f0 = f0 || s0;
        f1 = f1 || s1;
        f2 = f2 || s2;
        f3 = f3 || s3;

        // Evict-first streaming store (STG.E.128 + .CS policy), one per
        // step — the measured-optimal interleaved drain pattern.
        __stcs(op + (size_t)t * NQ, v);
    }
}

extern "C" void kernel_launch(void* const* d_in, const int* in_sizes, int n_in,
                              void* d_out, int out_size)
{
    const float* x    = (const float*)d_in[0];   // [2048, 1024] f32
    const float* sens = (const float*)d_in[1];   // [1024] f32
    float* out        = (float*)d_out;           // [2048, 64, 1024] f32

    const int total_threads = (B_DIM * N_DIM) / 4;  // 524288
    const int block = 256;
    const int grid  = total_threads / block;        // 2048

    ttfs_kernel<<<grid, block>>>(x, sens, out);
}